// round 1
// baseline (speedup 1.0000x reference)
#include <cuda_runtime.h>
#include <cuda_bf16.h>
#include <cstdint>
#include <cstdio>

// Problem constants
#define BB 4
#define LL 4096
#define DD 1024
#define WIDTH 3072          // 3*D
#define NFFT 8192           // 2*L
#define MTOT (BB*LL)        // 16384

// ---------------- scratch (static device arrays; no runtime allocation) ----------
__device__ float  g_u[(size_t)MTOT * WIDTH];        // u = x@W_in (+ later reused as nothing)
__device__ float  g_x0t[(size_t)BB * DD * LL];      // x0, transposed (B,D,L)
__device__ float  g_vgt[(size_t)BB * DD * LL];      // v*x1, transposed (B,D,L)
__device__ float  g_krt[(size_t)DD * LL];           // reversed filter, (D,L)
__device__ float2 g_hf[(size_t)DD * NFFT];          // FFT of reversed filter (bit-reversed order)
__device__ float  g_yt[(size_t)BB * DD * LL];       // (conv+bias)*x0, transposed (B,D,L)

// =================================================================================
// SGEMM (fp32 baseline): C[M,N] = A[M,K] @ B[K,N] + bias[N]
// BM=BN=128, BK=16, 256 threads, 8x8 per thread. All dims multiples of tiles.
// =================================================================================
#define BM 128
#define BN 128
#define BK 16

__global__ __launch_bounds__(256) void sgemm_nn(
    const float* __restrict__ A, const float* __restrict__ Bm,
    const float* __restrict__ bias, float* __restrict__ C,
    int M, int N, int K)
{
    __shared__ float As[BK][BM];
    __shared__ float Bs[BK][BN];
    const int bx = blockIdx.x;            // N tile
    const int by = blockIdx.y;            // M tile
    const int tid = threadIdx.x;
    const int tx = tid & 15;              // n
    const int ty = tid >> 4;              // m

    const float* Ab = A + (size_t)by * BM * K;
    const float* Bb = Bm + (size_t)bx * BN;

    float acc[8][8];
    #pragma unroll
    for (int i = 0; i < 8; ++i)
        #pragma unroll
        for (int j = 0; j < 8; ++j) acc[i][j] = 0.f;

    for (int kt = 0; kt < K; kt += BK) {
        // load A tile (row-major): 128x16 = 512 float4
        #pragma unroll
        for (int r = 0; r < 2; ++r) {
            int q = tid + r * 256;
            int row = q >> 2;
            int c4 = (q & 3) * 4;
            float4 v = *(const float4*)(Ab + (size_t)row * K + kt + c4);
            As[c4 + 0][row] = v.x;
            As[c4 + 1][row] = v.y;
            As[c4 + 2][row] = v.z;
            As[c4 + 3][row] = v.w;
        }
        // load B tile: 16x128 = 512 float4
        #pragma unroll
        for (int r = 0; r < 2; ++r) {
            int q = tid + r * 256;
            int row = q >> 5;
            int c4 = (q & 31) * 4;
            *(float4*)&Bs[row][c4] =
                *(const float4*)(Bb + (size_t)(kt + row) * N + c4);
        }
        __syncthreads();
        #pragma unroll
        for (int k = 0; k < BK; ++k) {
            float af[8], bf[8];
            *(float4*)&af[0] = *(float4*)&As[k][ty * 8];
            *(float4*)&af[4] = *(float4*)&As[k][ty * 8 + 4];
            *(float4*)&bf[0] = *(float4*)&Bs[k][tx * 8];
            *(float4*)&bf[4] = *(float4*)&Bs[k][tx * 8 + 4];
            #pragma unroll
            for (int i = 0; i < 8; ++i)
                #pragma unroll
                for (int j = 0; j < 8; ++j) acc[i][j] += af[i] * bf[j];
        }
        __syncthreads();
    }
    // epilogue + bias
    #pragma unroll
    for (int i = 0; i < 8; ++i) {
        size_t m = (size_t)by * BM + ty * 8 + i;
        #pragma unroll
        for (int j = 0; j < 8; j += 4) {
            int n = bx * BN + tx * 8 + j;
            float4 o;
            o.x = acc[i][j + 0] + bias[n + 0];
            o.y = acc[i][j + 1] + bias[n + 1];
            o.z = acc[i][j + 2] + bias[n + 2];
            o.w = acc[i][j + 3] + bias[n + 3];
            *(float4*)(C + m * N + n) = o;
        }
    }
}

// A is K-major with per-batch stride: element (m,k), m=b*batchL+t, lives at
// A[b*K*batchL + k*batchL + t]. BM tiles never cross batch boundaries.
__global__ __launch_bounds__(256) void sgemm_at(
    const float* __restrict__ A, const float* __restrict__ Bm,
    const float* __restrict__ bias, float* __restrict__ C,
    int M, int N, int K, int batchL)
{
    __shared__ float As[BK][BM];
    __shared__ float Bs[BK][BN];
    const int bx = blockIdx.x;
    const int by = blockIdx.y;
    const int tid = threadIdx.x;
    const int tx = tid & 15;
    const int ty = tid >> 4;

    const int m_start = by * BM;
    const int b = m_start / batchL;
    const int t0 = m_start % batchL;
    const float* Ab = A + (size_t)b * K * batchL + t0;
    const float* Bb = Bm + (size_t)bx * BN;

    float acc[8][8];
    #pragma unroll
    for (int i = 0; i < 8; ++i)
        #pragma unroll
        for (int j = 0; j < 8; ++j) acc[i][j] = 0.f;

    for (int kt = 0; kt < K; kt += BK) {
        // A tile: 16 k-rows x 128 m, contiguous in m
        #pragma unroll
        for (int r = 0; r < 2; ++r) {
            int q = tid + r * 256;
            int row = q >> 5;
            int c4 = (q & 31) * 4;
            *(float4*)&As[row][c4] =
                *(const float4*)(Ab + (size_t)(kt + row) * batchL + c4);
        }
        #pragma unroll
        for (int r = 0; r < 2; ++r) {
            int q = tid + r * 256;
            int row = q >> 5;
            int c4 = (q & 31) * 4;
            *(float4*)&Bs[row][c4] =
                *(const float4*)(Bb + (size_t)(kt + row) * N + c4);
        }
        __syncthreads();
        #pragma unroll
        for (int k = 0; k < BK; ++k) {
            float af[8], bf[8];
            *(float4*)&af[0] = *(float4*)&As[k][ty * 8];
            *(float4*)&af[4] = *(float4*)&As[k][ty * 8 + 4];
            *(float4*)&bf[0] = *(float4*)&Bs[k][tx * 8];
            *(float4*)&bf[4] = *(float4*)&Bs[k][tx * 8 + 4];
            #pragma unroll
            for (int i = 0; i < 8; ++i)
                #pragma unroll
                for (int j = 0; j < 8; ++j) acc[i][j] += af[i] * bf[j];
        }
        __syncthreads();
    }
    #pragma unroll
    for (int i = 0; i < 8; ++i) {
        size_t m = (size_t)by * BM + ty * 8 + i;
        #pragma unroll
        for (int j = 0; j < 8; j += 4) {
            int n = bx * BN + tx * 8 + j;
            float4 o;
            o.x = acc[i][j + 0] + bias[n + 0];
            o.y = acc[i][j + 1] + bias[n + 1];
            o.z = acc[i][j + 2] + bias[n + 2];
            o.w = acc[i][j + 3] + bias[n + 3];
            *(float4*)(C + m * N + n) = o;
        }
    }
}

// =================================================================================
// Short conv (3-tap causal, padding=2 truncated) + gate + transpose to (B,D,L)
//   uc[t,c] = w0[c]*u[t-2,c] + w1[c]*u[t-1,c] + w2[c]*u[t,c] + b[c]
//   x0 = uc[:, :D], x1 = uc[:, D:2D], v = uc[:, 2D:3D];  vg = v*x1
// grid (D/32, L/32, B), block (32,8)
// =================================================================================
__global__ void shortconv_kernel(
    const float* __restrict__ sw, const float* __restrict__ sb)
{
    __shared__ float sx0[32][33];
    __shared__ float sv[32][33];
    const int d0 = blockIdx.x * 32;
    const int t0 = blockIdx.y * 32;
    const int b  = blockIdx.z;
    const int tx = threadIdx.x;
    const int ty = threadIdx.y;
    const float* ub = g_u + (size_t)b * LL * WIDTH;

    #pragma unroll
    for (int r = 0; r < 4; ++r) {
        int t = t0 + ty + r * 8;
        int d = d0 + tx;
        float acc[3];
        #pragma unroll
        for (int seg = 0; seg < 3; ++seg) {
            int c = seg * DD + d;
            float w0 = sw[c * 3 + 0], w1 = sw[c * 3 + 1], w2 = sw[c * 3 + 2];
            float s = sb[c] + w2 * ub[(size_t)t * WIDTH + c];
            if (t >= 1) s += w1 * ub[(size_t)(t - 1) * WIDTH + c];
            if (t >= 2) s += w0 * ub[(size_t)(t - 2) * WIDTH + c];
            acc[seg] = s;
        }
        sx0[ty + r * 8][tx] = acc[0];
        sv [ty + r * 8][tx] = acc[2] * acc[1];
    }
    __syncthreads();
    #pragma unroll
    for (int r = 0; r < 4; ++r) {
        int d = d0 + ty + r * 8;
        int t = t0 + tx;
        size_t o = ((size_t)b * DD + d) * LL + t;
        g_x0t[o] = sx0[tx][ty + r * 8];
        g_vgt[o] = sv [tx][ty + r * 8];
    }
}

// =================================================================================
// Filter generation: positional encoding -> 2x sine MLP -> W3 -> exp decay.
// Writes the REVERSED kernel krt[d][m] = k[L-1-m, d], (D,L) layout.
// grid 4096 (one per t), block 256.
// =================================================================================
__global__ void filtergen_kernel(
    const float* __restrict__ W1, const float* __restrict__ b1, const float* __restrict__ f1,
    const float* __restrict__ W2, const float* __restrict__ b2, const float* __restrict__ f2,
    const float* __restrict__ W3, const float* __restrict__ b3)
{
    const int t = blockIdx.x;
    const int tid = threadIdx.x;
    __shared__ float h1[64], h2[64];

    const float tn = (float)t / (float)(LL - 1);
    const float ang = 6.2831853071795864769f * (float)t / (float)LL;
    const float phase = 1e-4f * ang;
    const float pe0 = tn, pe1 = cosf(phase), pe2 = -sinf(phase);

    if (tid < 64) {
        float z = pe0 * W1[0 * 64 + tid] + pe1 * W1[1 * 64 + tid] + pe2 * W1[2 * 64 + tid] + b1[tid];
        h1[tid] = sinf(z * f1[tid]);
    }
    __syncthreads();
    if (tid < 64) {
        float z = b2[tid];
        #pragma unroll 8
        for (int i = 0; i < 64; ++i) z += h1[i] * W2[i * 64 + tid];
        h2[tid] = sinf(z * f2[tid]);
    }
    __syncthreads();

    const float dmax = -15.350567286626975f;  // log(0.01)/0.3
    const float dmin = -3.0701134573253950f;  // log(0.01)/1.5
    #pragma unroll
    for (int r = 0; r < 4; ++r) {
        int d = tid + r * 256;
        float z = b3[d];
        #pragma unroll 8
        for (int i = 0; i < 64; ++i) z += h2[i] * W3[(size_t)i * DD + d];
        float delta = fabsf(dmax + (dmin - dmax) * ((float)d / (float)(DD - 1)));
        z *= expf(-tn * delta);
        g_krt[(size_t)d * LL + (LL - 1 - t)] = z;
    }
}

// =================================================================================
// 8192-pt complex FFT in shared memory.
// Forward: radix-2 DIF (natural in -> bit-reversed out).
// Inverse: radix-2 DIT w/ conj twiddles (bit-reversed in -> natural out).
// Pointwise multiply done in bit-reversed order on both sides -> no reversal pass.
// Shared: a[8192] float2 (64KB) + tw[4096] float2 (32KB) = 96KB dynamic.
// =================================================================================
extern __shared__ float2 fft_smem[];

__device__ __forceinline__ void fill_twiddles(float2* tw, int tid, int nthr) {
    for (int k = tid; k < 4096; k += nthr) {
        float sv, cv;
        sincospif((float)k / 4096.0f, &sv, &cv);   // exp(-i*pi*k/4096)
        tw[k] = make_float2(cv, -sv);
    }
}

__device__ __forceinline__ void fft_dif_fwd(float2* a, const float2* tw, int tid, int nthr) {
    #pragma unroll 1
    for (int s = 0; s < 13; ++s) {
        const int half = 4096 >> s;           // NFFT >> (s+1)
        __syncthreads();
        for (int i = tid; i < 4096; i += nthr) {
            int j = i & (half - 1);
            int blk = i >> (12 - s);
            int i0 = blk * (half << 1) + j;
            int i1 = i0 + half;
            float2 u = a[i0], v = a[i1];
            float2 d = make_float2(u.x - v.x, u.y - v.y);
            a[i0] = make_float2(u.x + v.x, u.y + v.y);
            float2 w = tw[j << s];
            a[i1] = make_float2(d.x * w.x - d.y * w.y, d.x * w.y + d.y * w.x);
        }
    }
    __syncthreads();
}

__device__ __forceinline__ void fft_dit_inv(float2* a, const float2* tw, int tid, int nthr) {
    #pragma unroll 1
    for (int s = 12; s >= 0; --s) {
        const int half = 4096 >> s;
        __syncthreads();
        for (int i = tid; i < 4096; i += nthr) {
            int j = i & (half - 1);
            int blk = i >> (12 - s);
            int i0 = blk * (half << 1) + j;
            int i1 = i0 + half;
            float2 w = tw[j << s];            // use conj(w)
            float2 q = a[i1];
            float2 v = make_float2(q.x * w.x + q.y * w.y, q.y * w.x - q.x * w.y);
            float2 u = a[i0];
            a[i0] = make_float2(u.x + v.x, u.y + v.y);
            a[i1] = make_float2(u.x - v.x, u.y - v.y);
        }
    }
    __syncthreads();
}

// Per-channel filter spectrum (bit-reversed order). grid D, block 512, 96KB smem.
__global__ void hf_kernel() {
    float2* a = fft_smem;
    float2* tw = fft_smem + NFFT;
    const int d = blockIdx.x;
    const int tid = threadIdx.x;
    const int nthr = blockDim.x;
    fill_twiddles(tw, tid, nthr);
    const float* src = g_krt + (size_t)d * LL;
    for (int i = tid; i < LL; i += nthr) a[i] = make_float2(src[i], 0.f);
    for (int i = LL + tid; i < NFFT; i += nthr) a[i] = make_float2(0.f, 0.f);
    fft_dif_fwd(a, tw, tid, nthr);
    float2* dst = g_hf + (size_t)d * NFFT;
    for (int i = tid; i < NFFT; i += nthr) dst[i] = a[i];
}

// FFT conv + filter bias + x0 gate. grid (D, B), block 512, 96KB smem.
__global__ void fftconv_kernel(const float* __restrict__ fbias) {
    float2* a = fft_smem;
    float2* tw = fft_smem + NFFT;
    const int d = blockIdx.x;
    const int b = blockIdx.y;
    const int tid = threadIdx.x;
    const int nthr = blockDim.x;
    fill_twiddles(tw, tid, nthr);

    const size_t ch = ((size_t)b * DD + d) * LL;
    const float* src = g_vgt + ch;
    for (int i = tid; i < LL; i += nthr) a[i] = make_float2(src[i], 0.f);
    for (int i = LL + tid; i < NFFT; i += nthr) a[i] = make_float2(0.f, 0.f);

    fft_dif_fwd(a, tw, tid, nthr);

    const float2* H = g_hf + (size_t)d * NFFT;
    for (int i = tid; i < NFFT; i += nthr) {
        float2 x = a[i], h = H[i];
        a[i] = make_float2(x.x * h.x - x.y * h.y, x.x * h.y + x.y * h.x);
    }

    fft_dit_inv(a, tw, tid, nthr);

    const float scale = 1.0f / (float)NFFT;
    const float fb = fbias[d];
    const float* x0 = g_x0t + ch;
    float* dst = g_yt + ch;
    for (int i = tid; i < LL; i += nthr)
        dst[i] = (a[i].x * scale + fb) * x0[i];
}

// =================================================================================
// launch
// =================================================================================
extern "C" void kernel_launch(void* const* d_in, const int* in_sizes, int n_in,
                              void* d_out, int out_size)
{
    const float* x       = (const float*)d_in[0];
    const float* W_in    = (const float*)d_in[1];
    const float* b_in    = (const float*)d_in[2];
    const float* short_w = (const float*)d_in[3];
    const float* short_b = (const float*)d_in[4];
    const float* W1      = (const float*)d_in[5];
    const float* b1      = (const float*)d_in[6];
    const float* f1      = (const float*)d_in[7];
    const float* W2      = (const float*)d_in[8];
    const float* b2      = (const float*)d_in[9];
    const float* f2      = (const float*)d_in[10];
    const float* W3      = (const float*)d_in[11];
    const float* b3      = (const float*)d_in[12];
    const float* fbias   = (const float*)d_in[13];
    const float* W_out   = (const float*)d_in[14];
    const float* b_out   = (const float*)d_in[15];
    float* out = (float*)d_out;

    // scratch addresses
    float*  p_u;   cudaGetSymbolAddress((void**)&p_u,   g_u);
    float*  p_yt;  cudaGetSymbolAddress((void**)&p_yt,  g_yt);

    // opt-in to 96KB dynamic smem for the FFT kernels (idempotent, cheap)
    cudaFuncSetAttribute(hf_kernel, cudaFuncAttributeMaxDynamicSharedMemorySize, 96 * 1024);
    cudaFuncSetAttribute(fftconv_kernel, cudaFuncAttributeMaxDynamicSharedMemorySize, 96 * 1024);

    // 1) u = x @ W_in + b_in           (16384 x 3072 x 1024)
    sgemm_nn<<<dim3(WIDTH / BN, MTOT / BM), 256>>>(x, W_in, b_in, p_u, MTOT, WIDTH, DD);

    // 2) short conv + gate + transpose -> g_x0t, g_vgt
    shortconv_kernel<<<dim3(DD / 32, LL / 32, BB), dim3(32, 8)>>>(short_w, short_b);

    // 3) filter generation (reversed) -> g_krt
    filtergen_kernel<<<LL, 256>>>(W1, b1, f1, W2, b2, f2, W3, b3);

    // 4) filter spectra -> g_hf
    hf_kernel<<<DD, 512, 96 * 1024>>>();

    // 5) FFT conv + bias + gate -> g_yt
    fftconv_kernel<<<dim3(DD, BB), 512, 96 * 1024>>>(fbias);

    // 6) out = y @ W_out + b_out       (16384 x 1024 x 1024), A is (B,D,L) K-major
    sgemm_at<<<dim3(DD / BN, MTOT / BM), 256>>>(p_yt, W_out, b_out, out, MTOT, DD, DD, LL);
}

// round 3
// speedup vs baseline: 2.1016x; 2.1016x over previous
#include <cuda_runtime.h>
#include <cuda_bf16.h>
#include <cstdint>
#include <cstdio>

#define BB 4
#define LL 4096
#define DD 1024
#define WIDTH 3072
#define NFFT 8192
#define MTOT (BB*LL)        // 16384

// ---------------- scratch -------------------------------------------------------
__device__ float  g_u[(size_t)MTOT * WIDTH];
__device__ float  g_xt[(size_t)DD * MTOT];          // x transposed, K-major
__device__ float  g_x0t[(size_t)BB * DD * LL];
__device__ float  g_vgt[(size_t)BB * DD * LL];
__device__ float  g_krt[(size_t)DD * LL];
__device__ float2 g_hf[(size_t)DD * NFFT];          // filter spectra (permuted order)
__device__ float  g_yt[(size_t)BB * DD * LL];

// =================================================================================
// 3xTF32 tensor-core GEMM:  C[M,N] = A^T-layout @ B + bias   (~fp32 accuracy)
// A is K-major: element (m,k), m = b*batchL + t, at A[b*K*batchL + k*batchL + t].
// 128x128 block, BK=16, 128 threads (4 warps of 64x64), cp.async double buffer.
// Each fragment element split hi/lo; 3 MMAs: hi*hi + hi*lo + lo*hi.
// =================================================================================
#define GPAD 136

__device__ __forceinline__ void cp16(uint32_t saddr, const float* g) {
    asm volatile("cp.async.cg.shared.global [%0], [%1], 16;\n" :: "r"(saddr), "l"(g));
}
__device__ __forceinline__ void mma8(float* c, const uint32_t* a, const uint32_t* b) {
    asm volatile(
        "mma.sync.aligned.m16n8k8.row.col.f32.tf32.tf32.f32 "
        "{%0,%1,%2,%3}, {%4,%5,%6,%7}, {%8,%9}, {%0,%1,%2,%3};\n"
        : "+f"(c[0]), "+f"(c[1]), "+f"(c[2]), "+f"(c[3])
        : "r"(a[0]), "r"(a[1]), "r"(a[2]), "r"(a[3]), "r"(b[0]), "r"(b[1]));
}
__device__ __forceinline__ void split32(float v, uint32_t& hi, uint32_t& lo) {
    uint32_t h = __float_as_uint(v) & 0xFFFFE000u;   // exact tf32 (13 low bits cleared)
    hi = h;
    lo = __float_as_uint(v - __uint_as_float(h));
}

__global__ __launch_bounds__(128) void gemm_tf32(
    const float* __restrict__ A, const float* __restrict__ Bm,
    const float* __restrict__ bias, float* __restrict__ C,
    int N, int K, int batchL)
{
    __shared__ __align__(16) float As[2][16][GPAD];
    __shared__ __align__(16) float Bs[2][16][GPAD];
    const int tid  = threadIdx.x;
    const int lane = tid & 31;
    const int warp = tid >> 5;
    const int wm = (warp >> 1) * 64;
    const int wn = (warp & 1) * 64;

    const int m_start = blockIdx.y * 128;
    const int b  = m_start / batchL;
    const int t0 = m_start % batchL;
    const float* Ab = A + (size_t)b * K * batchL + t0;
    const float* Bb = Bm + (size_t)blockIdx.x * 128;

    float c[4][8][4];
    #pragma unroll
    for (int mt = 0; mt < 4; ++mt)
        #pragma unroll
        for (int nt = 0; nt < 8; ++nt)
            #pragma unroll
            for (int q = 0; q < 4; ++q) c[mt][nt][q] = 0.f;

    const int niter = K / 16;
    auto issue = [&](int kt, int buf) {
        #pragma unroll
        for (int u = 0; u < 4; ++u) {
            int f = tid + u * 128;
            int row = f >> 5;
            int col = (f & 31) * 4;
            cp16((uint32_t)__cvta_generic_to_shared(&As[buf][row][col]),
                 Ab + (size_t)(kt + row) * batchL + col);
            cp16((uint32_t)__cvta_generic_to_shared(&Bs[buf][row][col]),
                 Bb + (size_t)(kt + row) * N + col);
        }
        asm volatile("cp.async.commit_group;\n");
    };

    issue(0, 0);
    for (int kt = 0; kt < niter; ++kt) {
        int cur = kt & 1;
        asm volatile("cp.async.wait_group 0;\n");
        __syncthreads();
        if (kt + 1 < niter) issue((kt + 1) * 16, cur ^ 1);

        #pragma unroll
        for (int k8 = 0; k8 < 16; k8 += 8) {
            uint32_t ah[4][4], al[4][4], bh[8][2], bl[8][2];
            const float* pa = &As[cur][k8 + (lane & 3)][wm + (lane >> 2)];
            #pragma unroll
            for (int mt = 0; mt < 4; ++mt) {
                split32(pa[mt * 16],            ah[mt][0], al[mt][0]);
                split32(pa[mt * 16 + 8],        ah[mt][1], al[mt][1]);
                split32(pa[4 * GPAD + mt * 16],     ah[mt][2], al[mt][2]);
                split32(pa[4 * GPAD + mt * 16 + 8], ah[mt][3], al[mt][3]);
            }
            const float* pb = &Bs[cur][k8 + (lane & 3)][wn + (lane >> 2)];
            #pragma unroll
            for (int nt = 0; nt < 8; ++nt) {
                split32(pb[nt * 8],            bh[nt][0], bl[nt][0]);
                split32(pb[4 * GPAD + nt * 8], bh[nt][1], bl[nt][1]);
            }
            #pragma unroll
            for (int mt = 0; mt < 4; ++mt)
                #pragma unroll
                for (int nt = 0; nt < 8; ++nt) {
                    mma8(c[mt][nt], ah[mt], bl[nt]);
                    mma8(c[mt][nt], al[mt], bh[nt]);
                    mma8(c[mt][nt], ah[mt], bh[nt]);
                }
        }
    }

    #pragma unroll
    for (int mt = 0; mt < 4; ++mt) {
        size_t r0 = (size_t)m_start + wm + mt * 16 + (lane >> 2);
        #pragma unroll
        for (int nt = 0; nt < 8; ++nt) {
            int col = blockIdx.x * 128 + wn + nt * 8 + (lane & 3) * 2;
            float2 bb = *(const float2*)(bias + col);
            float2 v0 = make_float2(c[mt][nt][0] + bb.x, c[mt][nt][1] + bb.y);
            float2 v1 = make_float2(c[mt][nt][2] + bb.x, c[mt][nt][3] + bb.y);
            *(float2*)(C + r0 * N + col) = v0;
            *(float2*)(C + (r0 + 8) * N + col) = v1;
        }
    }
}

// =================================================================================
// x transpose: (B*L, D) row-major -> g_xt[d][m]   (K-major for GEMM1)
// =================================================================================
__global__ void transpose_x(const float* __restrict__ x) {
    __shared__ float s[32][33];
    const int m0 = blockIdx.x * 32, d0 = blockIdx.y * 32;
    const int tx = threadIdx.x, ty = threadIdx.y;
    #pragma unroll
    for (int r = 0; r < 4; ++r)
        s[ty + r * 8][tx] = x[(size_t)(m0 + ty + r * 8) * DD + d0 + tx];
    __syncthreads();
    #pragma unroll
    for (int r = 0; r < 4; ++r)
        g_xt[(size_t)(d0 + ty + r * 8) * MTOT + m0 + tx] = s[tx][ty + r * 8];
}

// =================================================================================
// Short conv + gate + transpose to (B,D,L)
// =================================================================================
__global__ void shortconv_kernel(
    const float* __restrict__ sw, const float* __restrict__ sb)
{
    __shared__ float sx0[32][33];
    __shared__ float sv[32][33];
    const int d0 = blockIdx.x * 32;
    const int t0 = blockIdx.y * 32;
    const int b  = blockIdx.z;
    const int tx = threadIdx.x;
    const int ty = threadIdx.y;
    const float* ub = g_u + (size_t)b * LL * WIDTH;

    #pragma unroll
    for (int r = 0; r < 4; ++r) {
        int t = t0 + ty + r * 8;
        int d = d0 + tx;
        float acc[3];
        #pragma unroll
        for (int seg = 0; seg < 3; ++seg) {
            int cc = seg * DD + d;
            float w0 = sw[cc * 3 + 0], w1 = sw[cc * 3 + 1], w2 = sw[cc * 3 + 2];
            float s = sb[cc] + w2 * ub[(size_t)t * WIDTH + cc];
            if (t >= 1) s += w1 * ub[(size_t)(t - 1) * WIDTH + cc];
            if (t >= 2) s += w0 * ub[(size_t)(t - 2) * WIDTH + cc];
            acc[seg] = s;
        }
        sx0[ty + r * 8][tx] = acc[0];
        sv [ty + r * 8][tx] = acc[2] * acc[1];
    }
    __syncthreads();
    #pragma unroll
    for (int r = 0; r < 4; ++r) {
        int d = d0 + ty + r * 8;
        int t = t0 + tx;
        size_t o = ((size_t)b * DD + d) * LL + t;
        g_x0t[o] = sx0[tx][ty + r * 8];
        g_vgt[o] = sv [tx][ty + r * 8];
    }
}

// =================================================================================
// Filter generation (writes REVERSED kernel, (D,L))
// =================================================================================
__global__ void filtergen_kernel(
    const float* __restrict__ W1, const float* __restrict__ b1, const float* __restrict__ f1,
    const float* __restrict__ W2, const float* __restrict__ b2, const float* __restrict__ f2,
    const float* __restrict__ W3, const float* __restrict__ b3)
{
    const int t = blockIdx.x;
    const int tid = threadIdx.x;
    __shared__ float h1[64], h2[64];

    const float tn = (float)t / (float)(LL - 1);
    const float ang = 6.2831853071795864769f * (float)t / (float)LL;
    const float phase = 1e-4f * ang;
    const float pe0 = tn, pe1 = cosf(phase), pe2 = -sinf(phase);

    if (tid < 64) {
        float z = pe0 * W1[tid] + pe1 * W1[64 + tid] + pe2 * W1[128 + tid] + b1[tid];
        h1[tid] = sinf(z * f1[tid]);
    }
    __syncthreads();
    if (tid < 64) {
        float z = b2[tid];
        #pragma unroll 8
        for (int i = 0; i < 64; ++i) z += h1[i] * W2[i * 64 + tid];
        h2[tid] = sinf(z * f2[tid]);
    }
    __syncthreads();

    const float dmax = -15.350567286626975f;
    const float dmin = -3.0701134573253950f;
    #pragma unroll
    for (int r = 0; r < 4; ++r) {
        int d = tid + r * 256;
        float z = b3[d];
        #pragma unroll 8
        for (int i = 0; i < 64; ++i) z += h2[i] * W3[(size_t)i * DD + d];
        float delta = fabsf(dmax + (dmin - dmax) * ((float)d / (float)(DD - 1)));
        z *= expf(-tn * delta);
        g_krt[(size_t)d * LL + (LL - 1 - t)] = z;
    }
}

// =================================================================================
// 8192-pt FFT: 4 conflict-free radix-4 smem stages + register/shuffle 32-pt tail.
// smem: a[8192] float2 (64KB) + tw[2048] float2 (16KB) = 80KB.
// =================================================================================
__device__ __forceinline__ float2 cmul(float2 a, float2 b) {
    return make_float2(a.x * b.x - a.y * b.y, a.x * b.y + a.y * b.x);
}
__device__ __forceinline__ float2 cmulc(float2 a, float2 b) {   // a * conj(b)
    return make_float2(a.x * b.x + a.y * b.y, a.y * b.x - a.x * b.y);
}
__device__ __forceinline__ float2 shfx(float2 x, int h) {
    float2 o;
    o.x = __shfl_xor_sync(0xFFFFFFFFu, x.x, h);
    o.y = __shfl_xor_sync(0xFFFFFFFFu, x.y, h);
    return o;
}
__device__ __forceinline__ void fwd_stage(float2& x, int lane, int h, float2 w) {
    float2 o = shfx(x, h);
    if (lane & h) { float2 d = make_float2(o.x - x.x, o.y - x.y); x = cmul(d, w); }
    else          { x.x += o.x; x.y += o.y; }
}
__device__ __forceinline__ void inv_stage(float2& x, int lane, int h, float2 w) {
    float2 t = (lane & h) ? cmulc(x, w) : x;
    float2 o = shfx(t, h);
    if (lane & h) { x = make_float2(o.x - t.x, o.y - t.y); }
    else          { x = make_float2(t.x + o.x, t.y + o.y); }
}

template<int Q>
__device__ __forceinline__ void r4_fwd(float2* a, const float2* tw, int tid) {
    constexpr int STEP = 2048 / Q;
    #pragma unroll
    for (int i = tid; i < 2048; i += 512) {
        int j = i & (Q - 1);
        int blk = i / Q;
        int i0 = blk * (4 * Q) + j;
        float2 x0 = a[i0], x1 = a[i0 + Q], x2 = a[i0 + 2 * Q], x3 = a[i0 + 3 * Q];
        float2 t0 = make_float2(x0.x + x2.x, x0.y + x2.y);
        float2 t1 = make_float2(x0.x - x2.x, x0.y - x2.y);
        float2 t2 = make_float2(x1.x + x3.x, x1.y + x3.y);
        float2 t3 = make_float2(x1.x - x3.x, x1.y - x3.y);
        float2 b0 = make_float2(t0.x + t2.x, t0.y + t2.y);
        float2 b2 = make_float2(t0.x - t2.x, t0.y - t2.y);
        float2 b1 = make_float2(t1.x + t3.y, t1.y - t3.x);   // t1 - i*t3
        float2 b3 = make_float2(t1.x - t3.y, t1.y + t3.x);   // t1 + i*t3
        float2 w1 = tw[j * STEP];
        float2 w2 = cmul(w1, w1);
        float2 w3 = cmul(w1, w2);
        a[i0]         = b0;
        a[i0 + Q]     = cmul(b1, w1);
        a[i0 + 2 * Q] = cmul(b2, w2);
        a[i0 + 3 * Q] = cmul(b3, w3);
    }
    __syncthreads();
}

template<int Q>
__device__ __forceinline__ void r4_inv(float2* a, const float2* tw, int tid) {
    constexpr int STEP = 2048 / Q;
    #pragma unroll
    for (int i = tid; i < 2048; i += 512) {
        int j = i & (Q - 1);
        int blk = i / Q;
        int i0 = blk * (4 * Q) + j;
        float2 w1 = tw[j * STEP];
        float2 w2 = cmul(w1, w1);
        float2 w3 = cmul(w1, w2);
        float2 b0 = a[i0];
        float2 b1 = cmulc(a[i0 + Q], w1);
        float2 b2 = cmulc(a[i0 + 2 * Q], w2);
        float2 b3 = cmulc(a[i0 + 3 * Q], w3);
        float2 u0 = make_float2(b0.x + b2.x, b0.y + b2.y);
        float2 u1 = make_float2(b0.x - b2.x, b0.y - b2.y);
        float2 u2 = make_float2(b1.x + b3.x, b1.y + b3.y);
        float2 u3 = make_float2(b1.x - b3.x, b1.y - b3.y);
        a[i0]         = make_float2(u0.x + u2.x, u0.y + u2.y);
        a[i0 + 2 * Q] = make_float2(u0.x - u2.x, u0.y - u2.y);
        a[i0 + Q]     = make_float2(u1.x - u3.y, u1.y + u3.x);   // u1 + i*u3
        a[i0 + 3 * Q] = make_float2(u1.x + u3.y, u1.y - u3.x);   // u1 - i*u3
    }
    __syncthreads();
}

extern __shared__ float2 fft_smem[];

__device__ __forceinline__ void fill_tw(float2* tw, int tid) {
    for (int k = tid; k < 2048; k += 512) {
        float sv, cv;
        sincospif((float)k / 4096.0f, &sv, &cv);   // e^{-2*pi*i*k/8192}
        tw[k] = make_float2(cv, -sv);
    }
}

struct LaneTw { float2 w16, w8, w4, w2; };
__device__ __forceinline__ LaneTw make_lane_tw(int lane) {
    LaneTw lt;
    float s, c;
    sincospif((float)(lane & 15) / 16.0f, &s, &c); lt.w16 = make_float2(c, -s);
    sincospif((float)(lane & 7)  /  8.0f, &s, &c); lt.w8  = make_float2(c, -s);
    sincospif((float)(lane & 3)  /  4.0f, &s, &c); lt.w4  = make_float2(c, -s);
    sincospif((float)(lane & 1)  /  2.0f, &s, &c); lt.w2  = make_float2(c, -s);
    return lt;
}

// filter spectra. grid D, block 512, 80KB smem.
__global__ void hf_kernel() {
    float2* a = fft_smem;
    float2* tw = fft_smem + NFFT;
    const int d = blockIdx.x;
    const int tid = threadIdx.x;
    fill_tw(tw, tid);
    const float* src = g_krt + (size_t)d * LL;
    for (int i = tid; i < LL; i += 512) a[i] = make_float2(src[i], 0.f);
    for (int i = LL + tid; i < NFFT; i += 512) a[i] = make_float2(0.f, 0.f);
    __syncthreads();
    r4_fwd<2048>(a, tw, tid);
    r4_fwd<512>(a, tw, tid);
    r4_fwd<128>(a, tw, tid);
    r4_fwd<32>(a, tw, tid);

    const int lane = tid & 31, warp = tid >> 5;
    LaneTw lt = make_lane_tw(lane);
    const float2 one = make_float2(1.f, 0.f);
    float2* dst = g_hf + (size_t)d * NFFT;
    for (int c = warp * 16; c < warp * 16 + 16; ++c) {
        float2 x = a[c * 32 + lane];
        fwd_stage(x, lane, 16, lt.w16);
        fwd_stage(x, lane, 8,  lt.w8);
        fwd_stage(x, lane, 4,  lt.w4);
        fwd_stage(x, lane, 2,  lt.w2);
        fwd_stage(x, lane, 1,  one);
        dst[c * 32 + lane] = x;
    }
}

// FFT conv, 2 batches packed per FFT (real/imag). grid (D, 2), block 512, 80KB.
__global__ void fftconv_kernel(const float* __restrict__ fbias) {
    float2* a = fft_smem;
    float2* tw = fft_smem + NFFT;
    const int d  = blockIdx.x;
    const int pb = blockIdx.y;
    const int tid = threadIdx.x;
    fill_tw(tw, tid);

    const size_t ch0 = ((size_t)(2 * pb)     * DD + d) * LL;
    const size_t ch1 = ((size_t)(2 * pb + 1) * DD + d) * LL;
    const float* v0 = g_vgt + ch0;
    const float* v1 = g_vgt + ch1;
    for (int i = tid; i < LL; i += 512) a[i] = make_float2(v0[i], v1[i]);
    for (int i = LL + tid; i < NFFT; i += 512) a[i] = make_float2(0.f, 0.f);
    __syncthreads();

    r4_fwd<2048>(a, tw, tid);
    r4_fwd<512>(a, tw, tid);
    r4_fwd<128>(a, tw, tid);
    r4_fwd<32>(a, tw, tid);

    const int lane = tid & 31, warp = tid >> 5;
    LaneTw lt = make_lane_tw(lane);
    const float2 one = make_float2(1.f, 0.f);
    const float2* H = g_hf + (size_t)d * NFFT;
    for (int c = warp * 16; c < warp * 16 + 16; ++c) {
        float2 x = a[c * 32 + lane];
        fwd_stage(x, lane, 16, lt.w16);
        fwd_stage(x, lane, 8,  lt.w8);
        fwd_stage(x, lane, 4,  lt.w4);
        fwd_stage(x, lane, 2,  lt.w2);
        fwd_stage(x, lane, 1,  one);
        x = cmul(x, H[c * 32 + lane]);
        inv_stage(x, lane, 1,  one);
        inv_stage(x, lane, 2,  lt.w2);
        inv_stage(x, lane, 4,  lt.w4);
        inv_stage(x, lane, 8,  lt.w8);
        inv_stage(x, lane, 16, lt.w16);
        a[c * 32 + lane] = x;
    }
    __syncthreads();

    r4_inv<32>(a, tw, tid);
    r4_inv<128>(a, tw, tid);
    r4_inv<512>(a, tw, tid);
    r4_inv<2048>(a, tw, tid);

    const float scale = 1.0f / (float)NFFT;
    const float fb = fbias[d];
    const float* x00 = g_x0t + ch0;
    const float* x01 = g_x0t + ch1;
    float* y0 = g_yt + ch0;
    float* y1 = g_yt + ch1;
    for (int i = tid; i < LL; i += 512) {
        float2 r = a[i];
        y0[i] = (r.x * scale + fb) * x00[i];
        y1[i] = (r.y * scale + fb) * x01[i];
    }
}

// =================================================================================
// launch
// =================================================================================
extern "C" void kernel_launch(void* const* d_in, const int* in_sizes, int n_in,
                              void* d_out, int out_size)
{
    const float* x       = (const float*)d_in[0];
    const float* W_in    = (const float*)d_in[1];
    const float* b_in    = (const float*)d_in[2];
    const float* short_w = (const float*)d_in[3];
    const float* short_b = (const float*)d_in[4];
    const float* W1      = (const float*)d_in[5];
    const float* b1      = (const float*)d_in[6];
    const float* f1      = (const float*)d_in[7];
    const float* W2      = (const float*)d_in[8];
    const float* b2      = (const float*)d_in[9];
    const float* f2      = (const float*)d_in[10];
    const float* W3      = (const float*)d_in[11];
    const float* b3      = (const float*)d_in[12];
    const float* fbias   = (const float*)d_in[13];
    const float* W_out   = (const float*)d_in[14];
    const float* b_out   = (const float*)d_in[15];
    float* out = (float*)d_out;

    float* p_u;   cudaGetSymbolAddress((void**)&p_u,   g_u);
    float* p_xt;  cudaGetSymbolAddress((void**)&p_xt,  g_xt);
    float* p_yt;  cudaGetSymbolAddress((void**)&p_yt,  g_yt);

    cudaFuncSetAttribute(hf_kernel, cudaFuncAttributeMaxDynamicSharedMemorySize, 80 * 1024);
    cudaFuncSetAttribute(fftconv_kernel, cudaFuncAttributeMaxDynamicSharedMemorySize, 80 * 1024);

    // 0) transpose x -> K-major
    transpose_x<<<dim3(MTOT / 32, DD / 32), dim3(32, 8)>>>(x);

    // 1) u = x @ W_in + b_in   (3xTF32 tensor cores)
    gemm_tf32<<<dim3(WIDTH / 128, MTOT / 128), 128>>>(p_xt, W_in, b_in, p_u, WIDTH, DD, MTOT);

    // 2) short conv + gate + transpose
    shortconv_kernel<<<dim3(DD / 32, LL / 32, BB), dim3(32, 8)>>>(short_w, short_b);

    // 3) filter generation (reversed)
    filtergen_kernel<<<LL, 256>>>(W1, b1, f1, W2, b2, f2, W3, b3);

    // 4) filter spectra
    hf_kernel<<<DD, 512, 80 * 1024>>>();

    // 5) FFT conv (+bias, +gate), 2 batches per FFT
    fftconv_kernel<<<dim3(DD, 2), 512, 80 * 1024>>>(fbias);

    // 6) out = y @ W_out + b_out  (3xTF32)
    gemm_tf32<<<dim3(DD / 128, MTOT / 128), 128>>>(p_yt, W_out, b_out, out, DD, DD, LL);
}

// round 4
// speedup vs baseline: 2.6864x; 1.2782x over previous
#include <cuda_runtime.h>
#include <cuda_bf16.h>
#include <cstdint>
#include <cstdio>

#define BB 4
#define LL 4096
#define DD 1024
#define WIDTH 3072
#define NFFT 8192
#define MTOT (BB*LL)        // 16384

// ---------------- scratch -------------------------------------------------------
__device__ float  g_u[(size_t)MTOT * WIDTH];
__device__ float  g_xt[(size_t)DD * MTOT];          // x transposed, K-major
__device__ float  g_x0t[(size_t)BB * DD * LL];
__device__ float  g_vgt[(size_t)BB * DD * LL];
__device__ float  g_h2[(size_t)LL * 64];            // filter MLP hidden
__device__ float  g_krt[(size_t)DD * LL];
__device__ float2 g_hf[(size_t)DD * NFFT];          // filter spectra (permuted order)
__device__ float  g_yt[(size_t)BB * DD * LL];

// =================================================================================
// 3xBF16 tensor-core GEMM:  C[M,N] = A^T-layout @ B + bias   (~fp32 accuracy)
// A is K-major: (m,k), m = b*batchL + t, at A[b*K*batchL + k*batchL + t].
// 128x128 block, BK=16, 256 threads (8 warps of 64x32), cp.async double buffer.
// Split a = ah + al (bf16); C += Ah*Bh + Ah*Bl + Al*Bh via m16n8k16 bf16 MMA.
// =================================================================================
#define GPAD 136

__device__ __forceinline__ void cp16(uint32_t saddr, const float* g) {
    asm volatile("cp.async.cg.shared.global [%0], [%1], 16;\n" :: "r"(saddr), "l"(g));
}
__device__ __forceinline__ void mma16(float* c, const uint32_t* a, const uint32_t* b) {
    asm volatile(
        "mma.sync.aligned.m16n8k16.row.col.f32.bf16.bf16.f32 "
        "{%0,%1,%2,%3}, {%4,%5,%6,%7}, {%8,%9}, {%0,%1,%2,%3};\n"
        : "+f"(c[0]), "+f"(c[1]), "+f"(c[2]), "+f"(c[3])
        : "r"(a[0]), "r"(a[1]), "r"(a[2]), "r"(a[3]), "r"(b[0]), "r"(b[1]));
}
// pack two f32 (k, k+1) into bf16x2 hi + residual bf16x2 lo
__device__ __forceinline__ void split_pack(float v0, float v1, uint32_t& hi, uint32_t& lo) {
    uint32_t h;
    asm("cvt.rn.bf16x2.f32 %0, %1, %2;" : "=r"(h) : "f"(v1), "f"(v0));
    float r0 = __uint_as_float(h << 16);
    float r1 = __uint_as_float(h & 0xFFFF0000u);
    float l0 = v0 - r0, l1 = v1 - r1;
    uint32_t l;
    asm("cvt.rn.bf16x2.f32 %0, %1, %2;" : "=r"(l) : "f"(l1), "f"(l0));
    hi = h; lo = l;
}

__global__ __launch_bounds__(256) void gemm_bf16x3(
    const float* __restrict__ A, const float* __restrict__ Bm,
    const float* __restrict__ bias, float* __restrict__ C,
    int N, int K, int batchL)
{
    __shared__ __align__(16) float As[2][16][GPAD];
    __shared__ __align__(16) float Bs[2][16][GPAD];
    const int tid  = threadIdx.x;
    const int lane = tid & 31;
    const int warp = tid >> 5;
    const int wm = (warp >> 2) * 64;     // 2 m-groups
    const int wn = (warp & 3) * 32;      // 4 n-groups

    const int m_start = blockIdx.y * 128;
    const int b  = m_start / batchL;
    const int t0 = m_start % batchL;
    const float* Ab = A + (size_t)b * K * batchL + t0;
    const float* Bb = Bm + (size_t)blockIdx.x * 128;

    float c[4][4][4];
    #pragma unroll
    for (int mt = 0; mt < 4; ++mt)
        #pragma unroll
        for (int nt = 0; nt < 4; ++nt)
            #pragma unroll
            for (int q = 0; q < 4; ++q) c[mt][nt][q] = 0.f;

    const int niter = K / 16;
    auto issue = [&](int kt, int buf) {
        #pragma unroll
        for (int u = 0; u < 2; ++u) {
            int f = tid + u * 256;
            int row = f >> 5;
            int col = (f & 31) * 4;
            cp16((uint32_t)__cvta_generic_to_shared(&As[buf][row][col]),
                 Ab + (size_t)(kt + row) * batchL + col);
            cp16((uint32_t)__cvta_generic_to_shared(&Bs[buf][row][col]),
                 Bb + (size_t)(kt + row) * N + col);
        }
        asm volatile("cp.async.commit_group;\n");
    };

    issue(0, 0);
    for (int kt = 0; kt < niter; ++kt) {
        int cur = kt & 1;
        asm volatile("cp.async.wait_group 0;\n");
        __syncthreads();
        if (kt + 1 < niter) issue((kt + 1) * 16, cur ^ 1);

        const int kb = (lane & 3) * 2;        // k pair base
        const int mrow = wm + (lane >> 2);
        const int ncol = wn + (lane >> 2);

        uint32_t ah[4][4], al[4][4], bh[4][2], bl[4][2];
        #pragma unroll
        for (int mt = 0; mt < 4; ++mt) {
            int m = mrow + mt * 16;
            #pragma unroll
            for (int q = 0; q < 4; ++q) {
                int kk = kb + (q >> 1) * 8;
                int mm = m + (q & 1) * 8;
                split_pack(As[cur][kk][mm], As[cur][kk + 1][mm], ah[mt][q], al[mt][q]);
            }
        }
        #pragma unroll
        for (int nt = 0; nt < 4; ++nt) {
            int n = ncol + nt * 8;
            #pragma unroll
            for (int q = 0; q < 2; ++q) {
                int kk = kb + q * 8;
                split_pack(Bs[cur][kk][n], Bs[cur][kk + 1][n], bh[nt][q], bl[nt][q]);
            }
        }
        // three passes: hi*lo, lo*hi, hi*hi (dependent triplets maximally separated)
        #pragma unroll
        for (int mt = 0; mt < 4; ++mt)
            #pragma unroll
            for (int nt = 0; nt < 4; ++nt)
                mma16(c[mt][nt], ah[mt], bl[nt]);
        #pragma unroll
        for (int mt = 0; mt < 4; ++mt)
            #pragma unroll
            for (int nt = 0; nt < 4; ++nt)
                mma16(c[mt][nt], al[mt], bh[nt]);
        #pragma unroll
        for (int mt = 0; mt < 4; ++mt)
            #pragma unroll
            for (int nt = 0; nt < 4; ++nt)
                mma16(c[mt][nt], ah[mt], bh[nt]);
    }

    #pragma unroll
    for (int mt = 0; mt < 4; ++mt) {
        size_t r0 = (size_t)m_start + wm + mt * 16 + (lane >> 2);
        #pragma unroll
        for (int nt = 0; nt < 4; ++nt) {
            int col = blockIdx.x * 128 + wn + nt * 8 + (lane & 3) * 2;
            float2 bb = *(const float2*)(bias + col);
            float2 v0 = make_float2(c[mt][nt][0] + bb.x, c[mt][nt][1] + bb.y);
            float2 v1 = make_float2(c[mt][nt][2] + bb.x, c[mt][nt][3] + bb.y);
            *(float2*)(C + r0 * N + col) = v0;
            *(float2*)(C + (r0 + 8) * N + col) = v1;
        }
    }
}

// =================================================================================
// x transpose: (B*L, D) row-major -> g_xt[d][m]
// =================================================================================
__global__ void transpose_x(const float* __restrict__ x) {
    __shared__ float s[32][33];
    const int m0 = blockIdx.x * 32, d0 = blockIdx.y * 32;
    const int tx = threadIdx.x, ty = threadIdx.y;
    #pragma unroll
    for (int r = 0; r < 4; ++r)
        s[ty + r * 8][tx] = x[(size_t)(m0 + ty + r * 8) * DD + d0 + tx];
    __syncthreads();
    #pragma unroll
    for (int r = 0; r < 4; ++r)
        g_xt[(size_t)(d0 + ty + r * 8) * MTOT + m0 + tx] = s[tx][ty + r * 8];
}

// =================================================================================
// Short conv + gate + transpose to (B,D,L)
// =================================================================================
__global__ void shortconv_kernel(
    const float* __restrict__ sw, const float* __restrict__ sb)
{
    __shared__ float sx0[32][33];
    __shared__ float sv[32][33];
    const int d0 = blockIdx.x * 32;
    const int t0 = blockIdx.y * 32;
    const int b  = blockIdx.z;
    const int tx = threadIdx.x;
    const int ty = threadIdx.y;
    const float* ub = g_u + (size_t)b * LL * WIDTH;

    #pragma unroll
    for (int r = 0; r < 4; ++r) {
        int t = t0 + ty + r * 8;
        int d = d0 + tx;
        float acc[3];
        #pragma unroll
        for (int seg = 0; seg < 3; ++seg) {
            int cc = seg * DD + d;
            float w0 = sw[cc * 3 + 0], w1 = sw[cc * 3 + 1], w2 = sw[cc * 3 + 2];
            float s = sb[cc] + w2 * ub[(size_t)t * WIDTH + cc];
            if (t >= 1) s += w1 * ub[(size_t)(t - 1) * WIDTH + cc];
            if (t >= 2) s += w0 * ub[(size_t)(t - 2) * WIDTH + cc];
            acc[seg] = s;
        }
        sx0[ty + r * 8][tx] = acc[0];
        sv [ty + r * 8][tx] = acc[2] * acc[1];
    }
    __syncthreads();
    #pragma unroll
    for (int r = 0; r < 4; ++r) {
        int d = d0 + ty + r * 8;
        int t = t0 + tx;
        size_t o = ((size_t)b * DD + d) * LL + t;
        g_x0t[o] = sx0[tx][ty + r * 8];
        g_vgt[o] = sv [tx][ty + r * 8];
    }
}

// =================================================================================
// Filter gen phase 1: pe -> h1 -> h2   (one t per 64-thread block)
// =================================================================================
__global__ void filtergen_h2(
    const float* __restrict__ W1, const float* __restrict__ b1, const float* __restrict__ f1,
    const float* __restrict__ W2, const float* __restrict__ b2, const float* __restrict__ f2)
{
    const int t = blockIdx.x;
    const int tid = threadIdx.x;   // 64
    __shared__ float h1[64];

    const float tn = (float)t / (float)(LL - 1);
    const float ang = 6.2831853071795864769f * (float)t / (float)LL;
    const float phase = 1e-4f * ang;
    const float pe0 = tn, pe1 = cosf(phase), pe2 = -sinf(phase);

    float z = pe0 * W1[tid] + pe1 * W1[64 + tid] + pe2 * W1[128 + tid] + b1[tid];
    h1[tid] = sinf(z * f1[tid]);
    __syncthreads();
    float z2 = b2[tid];
    #pragma unroll 8
    for (int i = 0; i < 64; ++i) z2 += h1[i] * W2[i * 64 + tid];
    g_h2[(size_t)t * 64 + tid] = sinf(z2 * f2[tid]);
}

// =================================================================================
// Filter gen phase 2: k = h2 @ W3 + b3, * decay, write REVERSED (D,L).
// grid (L/64, D/128), block 256, smem: h2 tile 16KB + W3 tile 32KB.
// =================================================================================
__global__ __launch_bounds__(256) void filtergen_k(
    const float* __restrict__ W3, const float* __restrict__ b3)
{
    __shared__ float sh2[64][64];
    __shared__ float sw3[64][128];
    const int t0 = blockIdx.x * 64;
    const int d0 = blockIdx.y * 128;
    const int tid = threadIdx.x;

    for (int i = tid; i < 64 * 64; i += 256)
        sh2[i >> 6][i & 63] = g_h2[(size_t)(t0 + (i >> 6)) * 64 + (i & 63)];
    for (int i = tid; i < 64 * 128; i += 256)
        sw3[i >> 7][i & 127] = W3[(size_t)(i >> 7) * DD + d0 + (i & 127)];
    __syncthreads();

    const int dl0 = tid & 31;       // d lane
    const int tg  = (tid >> 5) * 8; // t group of 8
    float acc[4][8];
    #pragma unroll
    for (int dt = 0; dt < 4; ++dt) {
        float bv = b3[d0 + dl0 + dt * 32];
        #pragma unroll
        for (int tr = 0; tr < 8; ++tr) acc[dt][tr] = bv;
    }
    #pragma unroll 4
    for (int k = 0; k < 64; ++k) {
        float w[4], h[8];
        #pragma unroll
        for (int dt = 0; dt < 4; ++dt) w[dt] = sw3[k][dl0 + dt * 32];
        #pragma unroll
        for (int tr = 0; tr < 8; ++tr) h[tr] = sh2[tg + tr][k];
        #pragma unroll
        for (int dt = 0; dt < 4; ++dt)
            #pragma unroll
            for (int tr = 0; tr < 8; ++tr)
                acc[dt][tr] += h[tr] * w[dt];
    }

    const float dmax = -15.350567286626975f;
    const float dmin = -3.0701134573253950f;
    #pragma unroll
    for (int dt = 0; dt < 4; ++dt) {
        int d = d0 + dl0 + dt * 32;
        float delta = fabsf(dmax + (dmin - dmax) * ((float)d / (float)(DD - 1)));
        #pragma unroll
        for (int tr = 0; tr < 8; ++tr) {
            int t = t0 + tg + tr;
            float tn = (float)t / (float)(LL - 1);
            g_krt[(size_t)d * LL + (LL - 1 - t)] = acc[dt][tr] * expf(-tn * delta);
        }
    }
}

// =================================================================================
// 8192-pt FFT: 4 conflict-free radix-4 smem stages + register/shuffle 32-pt tail.
// smem: a[8192] float2 (64KB) + tw[2048] float2 (16KB) = 80KB.
// =================================================================================
__device__ __forceinline__ float2 cmul(float2 a, float2 b) {
    return make_float2(a.x * b.x - a.y * b.y, a.x * b.y + a.y * b.x);
}
__device__ __forceinline__ float2 cmulc(float2 a, float2 b) {   // a * conj(b)
    return make_float2(a.x * b.x + a.y * b.y, a.y * b.x - a.x * b.y);
}
__device__ __forceinline__ float2 shfx(float2 x, int h) {
    float2 o;
    o.x = __shfl_xor_sync(0xFFFFFFFFu, x.x, h);
    o.y = __shfl_xor_sync(0xFFFFFFFFu, x.y, h);
    return o;
}
__device__ __forceinline__ void fwd_stage(float2& x, int lane, int h, float2 w) {
    float2 o = shfx(x, h);
    if (lane & h) { float2 d = make_float2(o.x - x.x, o.y - x.y); x = cmul(d, w); }
    else          { x.x += o.x; x.y += o.y; }
}
__device__ __forceinline__ void inv_stage(float2& x, int lane, int h, float2 w) {
    float2 t = (lane & h) ? cmulc(x, w) : x;
    float2 o = shfx(t, h);
    if (lane & h) { x = make_float2(o.x - t.x, o.y - t.y); }
    else          { x = make_float2(t.x + o.x, t.y + o.y); }
}

template<int Q>
__device__ __forceinline__ void r4_fwd(float2* a, const float2* tw, int tid) {
    constexpr int STEP = 2048 / Q;
    #pragma unroll
    for (int i = tid; i < 2048; i += 512) {
        int j = i & (Q - 1);
        int blk = i / Q;
        int i0 = blk * (4 * Q) + j;
        float2 x0 = a[i0], x1 = a[i0 + Q], x2 = a[i0 + 2 * Q], x3 = a[i0 + 3 * Q];
        float2 t0 = make_float2(x0.x + x2.x, x0.y + x2.y);
        float2 t1 = make_float2(x0.x - x2.x, x0.y - x2.y);
        float2 t2 = make_float2(x1.x + x3.x, x1.y + x3.y);
        float2 t3 = make_float2(x1.x - x3.x, x1.y - x3.y);
        float2 b0 = make_float2(t0.x + t2.x, t0.y + t2.y);
        float2 b2 = make_float2(t0.x - t2.x, t0.y - t2.y);
        float2 b1 = make_float2(t1.x + t3.y, t1.y - t3.x);   // t1 - i*t3
        float2 b3 = make_float2(t1.x - t3.y, t1.y + t3.x);   // t1 + i*t3
        float2 w1 = tw[j * STEP];
        float2 w2 = cmul(w1, w1);
        float2 w3 = cmul(w1, w2);
        a[i0]         = b0;
        a[i0 + Q]     = cmul(b1, w1);
        a[i0 + 2 * Q] = cmul(b2, w2);
        a[i0 + 3 * Q] = cmul(b3, w3);
    }
    __syncthreads();
}

template<int Q>
__device__ __forceinline__ void r4_inv(float2* a, const float2* tw, int tid) {
    constexpr int STEP = 2048 / Q;
    #pragma unroll
    for (int i = tid; i < 2048; i += 512) {
        int j = i & (Q - 1);
        int blk = i / Q;
        int i0 = blk * (4 * Q) + j;
        float2 w1 = tw[j * STEP];
        float2 w2 = cmul(w1, w1);
        float2 w3 = cmul(w1, w2);
        float2 b0 = a[i0];
        float2 b1 = cmulc(a[i0 + Q], w1);
        float2 b2 = cmulc(a[i0 + 2 * Q], w2);
        float2 b3 = cmulc(a[i0 + 3 * Q], w3);
        float2 u0 = make_float2(b0.x + b2.x, b0.y + b2.y);
        float2 u1 = make_float2(b0.x - b2.x, b0.y - b2.y);
        float2 u2 = make_float2(b1.x + b3.x, b1.y + b3.y);
        float2 u3 = make_float2(b1.x - b3.x, b1.y - b3.y);
        a[i0]         = make_float2(u0.x + u2.x, u0.y + u2.y);
        a[i0 + 2 * Q] = make_float2(u0.x - u2.x, u0.y - u2.y);
        a[i0 + Q]     = make_float2(u1.x - u3.y, u1.y + u3.x);   // u1 + i*u3
        a[i0 + 3 * Q] = make_float2(u1.x + u3.y, u1.y - u3.x);   // u1 - i*u3
    }
    __syncthreads();
}

extern __shared__ float2 fft_smem[];

__device__ __forceinline__ void fill_tw(float2* tw, int tid) {
    for (int k = tid; k < 2048; k += 512) {
        float sv, cv;
        sincospif((float)k / 4096.0f, &sv, &cv);   // e^{-2*pi*i*k/8192}
        tw[k] = make_float2(cv, -sv);
    }
}

struct LaneTw { float2 w16, w8, w4, w2; };
__device__ __forceinline__ LaneTw make_lane_tw(int lane) {
    LaneTw lt;
    float s, c;
    sincospif((float)(lane & 15) / 16.0f, &s, &c); lt.w16 = make_float2(c, -s);
    sincospif((float)(lane & 7)  /  8.0f, &s, &c); lt.w8  = make_float2(c, -s);
    sincospif((float)(lane & 3)  /  4.0f, &s, &c); lt.w4  = make_float2(c, -s);
    sincospif((float)(lane & 1)  /  2.0f, &s, &c); lt.w2  = make_float2(c, -s);
    return lt;
}

// filter spectra. grid D, block 512, 80KB smem.
__global__ void hf_kernel() {
    float2* a = fft_smem;
    float2* tw = fft_smem + NFFT;
    const int d = blockIdx.x;
    const int tid = threadIdx.x;
    fill_tw(tw, tid);
    const float* src = g_krt + (size_t)d * LL;
    for (int i = tid; i < LL; i += 512) a[i] = make_float2(src[i], 0.f);
    for (int i = LL + tid; i < NFFT; i += 512) a[i] = make_float2(0.f, 0.f);
    __syncthreads();
    r4_fwd<2048>(a, tw, tid);
    r4_fwd<512>(a, tw, tid);
    r4_fwd<128>(a, tw, tid);
    r4_fwd<32>(a, tw, tid);

    const int lane = tid & 31, warp = tid >> 5;
    LaneTw lt = make_lane_tw(lane);
    const float2 one = make_float2(1.f, 0.f);
    float2* dst = g_hf + (size_t)d * NFFT;
    for (int c = warp * 16; c < warp * 16 + 16; ++c) {
        float2 x = a[c * 32 + lane];
        fwd_stage(x, lane, 16, lt.w16);
        fwd_stage(x, lane, 8,  lt.w8);
        fwd_stage(x, lane, 4,  lt.w4);
        fwd_stage(x, lane, 2,  lt.w2);
        fwd_stage(x, lane, 1,  one);
        dst[c * 32 + lane] = x;
    }
}

// FFT conv, 2 batches packed per FFT (real/imag). grid (D, 2), block 512, 80KB.
__global__ void fftconv_kernel(const float* __restrict__ fbias) {
    float2* a = fft_smem;
    float2* tw = fft_smem + NFFT;
    const int d  = blockIdx.x;
    const int pb = blockIdx.y;
    const int tid = threadIdx.x;
    fill_tw(tw, tid);

    const size_t ch0 = ((size_t)(2 * pb)     * DD + d) * LL;
    const size_t ch1 = ((size_t)(2 * pb + 1) * DD + d) * LL;
    const float* v0 = g_vgt + ch0;
    const float* v1 = g_vgt + ch1;
    for (int i = tid; i < LL; i += 512) a[i] = make_float2(v0[i], v1[i]);
    for (int i = LL + tid; i < NFFT; i += 512) a[i] = make_float2(0.f, 0.f);
    __syncthreads();

    r4_fwd<2048>(a, tw, tid);
    r4_fwd<512>(a, tw, tid);
    r4_fwd<128>(a, tw, tid);
    r4_fwd<32>(a, tw, tid);

    const int lane = tid & 31, warp = tid >> 5;
    LaneTw lt = make_lane_tw(lane);
    const float2 one = make_float2(1.f, 0.f);
    const float2* H = g_hf + (size_t)d * NFFT;
    for (int c = warp * 16; c < warp * 16 + 16; ++c) {
        float2 x = a[c * 32 + lane];
        fwd_stage(x, lane, 16, lt.w16);
        fwd_stage(x, lane, 8,  lt.w8);
        fwd_stage(x, lane, 4,  lt.w4);
        fwd_stage(x, lane, 2,  lt.w2);
        fwd_stage(x, lane, 1,  one);
        x = cmul(x, H[c * 32 + lane]);
        inv_stage(x, lane, 1,  one);
        inv_stage(x, lane, 2,  lt.w2);
        inv_stage(x, lane, 4,  lt.w4);
        inv_stage(x, lane, 8,  lt.w8);
        inv_stage(x, lane, 16, lt.w16);
        a[c * 32 + lane] = x;
    }
    __syncthreads();

    r4_inv<32>(a, tw, tid);
    r4_inv<128>(a, tw, tid);
    r4_inv<512>(a, tw, tid);
    r4_inv<2048>(a, tw, tid);

    const float scale = 1.0f / (float)NFFT;
    const float fb = fbias[d];
    const float* x00 = g_x0t + ch0;
    const float* x01 = g_x0t + ch1;
    float* y0 = g_yt + ch0;
    float* y1 = g_yt + ch1;
    for (int i = tid; i < LL; i += 512) {
        float2 r = a[i];
        y0[i] = (r.x * scale + fb) * x00[i];
        y1[i] = (r.y * scale + fb) * x01[i];
    }
}

// =================================================================================
// launch
// =================================================================================
extern "C" void kernel_launch(void* const* d_in, const int* in_sizes, int n_in,
                              void* d_out, int out_size)
{
    const float* x       = (const float*)d_in[0];
    const float* W_in    = (const float*)d_in[1];
    const float* b_in    = (const float*)d_in[2];
    const float* short_w = (const float*)d_in[3];
    const float* short_b = (const float*)d_in[4];
    const float* W1      = (const float*)d_in[5];
    const float* b1      = (const float*)d_in[6];
    const float* f1      = (const float*)d_in[7];
    const float* W2      = (const float*)d_in[8];
    const float* b2      = (const float*)d_in[9];
    const float* f2      = (const float*)d_in[10];
    const float* W3      = (const float*)d_in[11];
    const float* b3      = (const float*)d_in[12];
    const float* fbias   = (const float*)d_in[13];
    const float* W_out   = (const float*)d_in[14];
    const float* b_out   = (const float*)d_in[15];
    float* out = (float*)d_out;

    float* p_u;   cudaGetSymbolAddress((void**)&p_u,   g_u);
    float* p_xt;  cudaGetSymbolAddress((void**)&p_xt,  g_xt);
    float* p_yt;  cudaGetSymbolAddress((void**)&p_yt,  g_yt);

    cudaFuncSetAttribute(hf_kernel, cudaFuncAttributeMaxDynamicSharedMemorySize, 80 * 1024);
    cudaFuncSetAttribute(fftconv_kernel, cudaFuncAttributeMaxDynamicSharedMemorySize, 80 * 1024);

    // 0) transpose x -> K-major
    transpose_x<<<dim3(MTOT / 32, DD / 32), dim3(32, 8)>>>(x);

    // 1) u = x @ W_in + b_in   (3xBF16 tensor cores)
    gemm_bf16x3<<<dim3(WIDTH / 128, MTOT / 128), 256>>>(p_xt, W_in, b_in, p_u, WIDTH, DD, MTOT);

    // 2) short conv + gate + transpose
    shortconv_kernel<<<dim3(DD / 32, LL / 32, BB), dim3(32, 8)>>>(short_w, short_b);

    // 3) filter generation: MLP hidden, then W3 + decay (reversed)
    filtergen_h2<<<LL, 64>>>(W1, b1, f1, W2, b2, f2);
    filtergen_k<<<dim3(LL / 64, DD / 128), 256>>>(W3, b3);

    // 4) filter spectra
    hf_kernel<<<DD, 512, 80 * 1024>>>();

    // 5) FFT conv (+bias, +gate), 2 batches per FFT
    fftconv_kernel<<<dim3(DD, 2), 512, 80 * 1024>>>(fbias);

    // 6) out = y @ W_out + b_out  (3xBF16)
    gemm_bf16x3<<<dim3(DD / 128, MTOT / 128), 256>>>(p_yt, W_out, b_out, out, DD, DD, LL);
}